// round 7
// baseline (speedup 1.0000x reference)
#include <cuda_runtime.h>
#include <cstdint>

// Problem constants (fixed by the dataset): B=2, S=4096, H=1024, I=512, E=8
#define T_TOK   8192
#define H_DIM   1024
#define I_DIM   512
#define E_NUM   8

// GEMM tiling
#define BM      128
#define BN      64
#define BK      32
#define KPAD    36              // BK + 4 padding -> conflict-free fragment LDS
#define MAXTILES 72             // sum ceil(n_e/BM) <= T/BM + (E-1) = 71
#define PERM_N  (T_TOK + E_NUM * BM)   // 9216 padded permuted rows

// ---------------- device scratch (no allocations allowed) ----------------
__device__ int   g_sel[T_TOK];
__device__ float g_rw[T_TOK];
__device__ int   g_counts[E_NUM];
__device__ int   g_fill[E_NUM];
__device__ int   g_expStart[E_NUM];
__device__ int   g_perm[PERM_N];
__device__ int   g_tileExpert[MAXTILES];
__device__ int   g_tileRow[MAXTILES];
__device__ int   g_numTiles;
__device__ float g_act[(size_t)PERM_N * I_DIM];   // ~18.9 MB permuted intermediate

// ---------------- helpers ----------------
__device__ __forceinline__ uint32_t f2tf32(float x) {
    uint32_t r;
    asm("cvt.rna.tf32.f32 %0, %1;" : "=r"(r) : "f"(x));
    return r;
}

// D += A*B, m16n8k8 tf32, A row-major (MxK), B col-major (KxN == weight row n contiguous in K)
__device__ __forceinline__ void mma8(float* acc, const uint32_t* a, const uint32_t* b) {
    asm volatile(
        "mma.sync.aligned.m16n8k8.row.col.f32.tf32.tf32.f32 "
        "{%0,%1,%2,%3}, {%4,%5,%6,%7}, {%8,%9}, {%0,%1,%2,%3};\n"
        : "+f"(acc[0]), "+f"(acc[1]), "+f"(acc[2]), "+f"(acc[3])
        : "r"(a[0]), "r"(a[1]), "r"(a[2]), "r"(a[3]), "r"(b[0]), "r"(b[1]));
}

// ---------------- kernel 0: reset scratch ----------------
__global__ void k_init() {
    int i = blockIdx.x * blockDim.x + threadIdx.x;
    if (i < PERM_N) g_perm[i] = -1;
    if (i < E_NUM) { g_counts[i] = 0; g_fill[i] = 0; }
}

// ---------------- kernel 1: router (1 warp / token) ----------------
__global__ __launch_bounds__(256) void k_router(const float* __restrict__ hs,
                                                const float* __restrict__ gate_w) {
    int warp = (blockIdx.x * 256 + threadIdx.x) >> 5;
    int lane = threadIdx.x & 31;
    if (warp >= T_TOK) return;
    const float* xr = hs + (size_t)warp * H_DIM;

    float xv[32];
#pragma unroll
    for (int i = 0; i < 32; i++) xv[i] = xr[lane + 32 * i];

    float acc[E_NUM];
#pragma unroll
    for (int e = 0; e < E_NUM; e++) {
        const float* w = gate_w + e * H_DIM;
        float s = 0.f;
#pragma unroll
        for (int i = 0; i < 32; i++) s = fmaf(xv[i], w[lane + 32 * i], s);
        acc[e] = s;
    }
#pragma unroll
    for (int e = 0; e < E_NUM; e++) {
#pragma unroll
        for (int o = 16; o > 0; o >>= 1) acc[e] += __shfl_xor_sync(0xffffffffu, acc[e], o);
    }
    // first-max argmax (matches jnp.argmax tie rule)
    int best = 0; float bv = acc[0];
#pragma unroll
    for (int e = 1; e < E_NUM; e++) { if (acc[e] > bv) { bv = acc[e]; best = e; } }

    if (lane == 0) {
        g_sel[warp] = best;
        g_rw[warp]  = 1.f / (1.f + expf(-bv));
        atomicAdd(&g_counts[best], 1);
    }
}

// ---------------- kernel 2: plan (single thread) ----------------
__global__ void k_plan() {
    int rowOff = 0, tiles = 0;
    for (int e = 0; e < E_NUM; e++) {
        g_expStart[e] = rowOff;
        int c  = g_counts[e];
        int nt = (c + BM - 1) / BM;
        for (int t = 0; t < nt; t++) {
            g_tileExpert[tiles] = e;
            g_tileRow[tiles]    = rowOff;
            rowOff += BM;
            tiles++;
        }
    }
    g_numTiles = tiles;
}

// ---------------- kernel 3: scatter tokens into padded per-expert segments ----------------
__global__ void k_scatter() {
    int t = blockIdx.x * blockDim.x + threadIdx.x;
    if (t >= T_TOK) return;
    int e   = g_sel[t];
    int pos = g_expStart[e] + atomicAdd(&g_fill[e], 1);
    g_perm[pos] = t;
}

// ---------------- kernel 4: fused gate+up GEMM + SiLU  (act = up * silu(gate)) ----------------
// A[rows=permuted tokens, K=H] gathered+scaled by routing weight; B = w_gate[e], w_up[e] ([I,H] row-major)
__global__ __launch_bounds__(256) void k_gemm1(const float* __restrict__ hs,
                                               const float* __restrict__ w_gate,
                                               const float* __restrict__ w_up) {
    if ((int)blockIdx.x >= g_numTiles) return;
    const int mt = blockIdx.x, nt = blockIdx.y;
    const int e       = g_tileExpert[mt];
    const int rowBase = g_tileRow[mt];
    const float* Wg = w_gate + (size_t)e * I_DIM * H_DIM;
    const float* Wu = w_up   + (size_t)e * I_DIM * H_DIM;
    const int nBase = nt * BN;

    __shared__ uint32_t sA[BM][KPAD];
    __shared__ uint32_t sG[BN][KPAD];
    __shared__ uint32_t sU[BN][KPAD];

    const int tid = threadIdx.x;

    // per-thread A sources (gather via perm, scale folded in)
    const float* aP[4]; float aSc[4];
#pragma unroll
    for (int l = 0; l < 4; l++) {
        int idx = tid + l * 256;
        int r = idx >> 3, c4 = (idx & 7) * 4;
        int tok = g_perm[rowBase + r];
        if (tok >= 0) { aP[l] = hs + (size_t)tok * H_DIM + c4; aSc[l] = g_rw[tok]; }
        else          { aP[l] = nullptr;                        aSc[l] = 0.f;      }
    }
    const float* gP[2]; const float* uP[2];
#pragma unroll
    for (int l = 0; l < 2; l++) {
        int idx = tid + l * 256;
        int n = idx >> 3, c4 = (idx & 7) * 4;
        gP[l] = Wg + (size_t)(nBase + n) * H_DIM + c4;
        uP[l] = Wu + (size_t)(nBase + n) * H_DIM + c4;
    }

    const int lane = tid & 31, warp = tid >> 5;
    const int wm = (warp & 3) * 32;     // 4 warps along M
    const int wn = (warp >> 2) * 32;    // 2 warps along N
    const int gID = lane >> 2, tig = lane & 3;

    float accG[2][4][4], accU[2][4][4];
#pragma unroll
    for (int mi = 0; mi < 2; mi++)
#pragma unroll
        for (int ni = 0; ni < 4; ni++)
#pragma unroll
            for (int j = 0; j < 4; j++) { accG[mi][ni][j] = 0.f; accU[mi][ni][j] = 0.f; }

    for (int k0 = 0; k0 < H_DIM; k0 += BK) {
#pragma unroll
        for (int l = 0; l < 4; l++) {
            int idx = tid + l * 256;
            int r = idx >> 3, c4 = (idx & 7) * 4;
            float4 v = aP[l] ? *(const float4*)(aP[l] + k0) : make_float4(0.f, 0.f, 0.f, 0.f);
            uint4 u;
            u.x = f2tf32(v.x * aSc[l]); u.y = f2tf32(v.y * aSc[l]);
            u.z = f2tf32(v.z * aSc[l]); u.w = f2tf32(v.w * aSc[l]);
            *(uint4*)&sA[r][c4] = u;
        }
#pragma unroll
        for (int l = 0; l < 2; l++) {
            int idx = tid + l * 256;
            int n = idx >> 3, c4 = (idx & 7) * 4;
            float4 v = *(const float4*)(gP[l] + k0);
            uint4 u; u.x = f2tf32(v.x); u.y = f2tf32(v.y); u.z = f2tf32(v.z); u.w = f2tf32(v.w);
            *(uint4*)&sG[n][c4] = u;
            float4 w = *(const float4*)(uP[l] + k0);
            uint4 t; t.x = f2tf32(w.x); t.y = f2tf32(w.y); t.z = f2tf32(w.z); t.w = f2tf32(w.w);
            *(uint4*)&sU[n][c4] = t;
        }
        __syncthreads();
#pragma unroll
        for (int kk = 0; kk < BK; kk += 8) {
            uint32_t a[2][4];
#pragma unroll
            for (int mi = 0; mi < 2; mi++) {
                int row = wm + mi * 16 + gID;
                a[mi][0] = sA[row][kk + tig];
                a[mi][1] = sA[row + 8][kk + tig];
                a[mi][2] = sA[row][kk + tig + 4];
                a[mi][3] = sA[row + 8][kk + tig + 4];
            }
#pragma unroll
            for (int ni = 0; ni < 4; ni++) {
                int n = wn + ni * 8 + gID;
                uint32_t bg[2] = { sG[n][kk + tig], sG[n][kk + tig + 4] };
                uint32_t bu[2] = { sU[n][kk + tig], sU[n][kk + tig + 4] };
#pragma unroll
                for (int mi = 0; mi < 2; mi++) {
                    mma8(accG[mi][ni], a[mi], bg);
                    mma8(accU[mi][ni], a[mi], bu);
                }
            }
        }
        __syncthreads();
    }

    // epilogue: act = up * silu(gate), stored in permuted layout
#pragma unroll
    for (int mi = 0; mi < 2; mi++) {
#pragma unroll
        for (int ni = 0; ni < 4; ni++) {
#pragma unroll
            for (int half = 0; half < 2; half++) {
                int row = wm + mi * 16 + gID + half * 8;
                int col = nBase + wn + ni * 8 + tig * 2;
                float g0 = accG[mi][ni][half * 2 + 0], g1 = accG[mi][ni][half * 2 + 1];
                float u0 = accU[mi][ni][half * 2 + 0], u1 = accU[mi][ni][half * 2 + 1];
                float a0 = u0 * (g0 / (1.f + __expf(-g0)));
                float a1 = u1 * (g1 / (1.f + __expf(-g1)));
                *(float2*)&g_act[(size_t)(rowBase + row) * I_DIM + col] = make_float2(a0, a1);
            }
        }
    }
}

// ---------------- kernel 5: down GEMM + scatter back ----------------
// A = g_act (permuted rows, K=I), B = w_down[e] ([H,I] row-major), out[tok] = A @ B^T
__global__ __launch_bounds__(256) void k_gemm2(const float* __restrict__ w_down,
                                               float* __restrict__ out) {
    if ((int)blockIdx.x >= g_numTiles) return;
    const int mt = blockIdx.x, nt = blockIdx.y;
    const int e       = g_tileExpert[mt];
    const int rowBase = g_tileRow[mt];
    const float* Wd = w_down + (size_t)e * H_DIM * I_DIM;
    const int nBase = nt * BN;

    __shared__ uint32_t sA[BM][KPAD];
    __shared__ uint32_t sB[BN][KPAD];
    __shared__ int sTok[BM];

    const int tid = threadIdx.x;
    if (tid < BM) sTok[tid] = g_perm[rowBase + tid];

    const float* aP[4];
#pragma unroll
    for (int l = 0; l < 4; l++) {
        int idx = tid + l * 256;
        int r = idx >> 3, c4 = (idx & 7) * 4;
        aP[l] = g_act + (size_t)(rowBase + r) * I_DIM + c4;
    }
    const float* bP[2];
#pragma unroll
    for (int l = 0; l < 2; l++) {
        int idx = tid + l * 256;
        int n = idx >> 3, c4 = (idx & 7) * 4;
        bP[l] = Wd + (size_t)(nBase + n) * I_DIM + c4;
    }

    const int lane = tid & 31, warp = tid >> 5;
    const int wm = (warp & 3) * 32, wn = (warp >> 2) * 32;
    const int gID = lane >> 2, tig = lane & 3;

    float acc[2][4][4];
#pragma unroll
    for (int mi = 0; mi < 2; mi++)
#pragma unroll
        for (int ni = 0; ni < 4; ni++)
#pragma unroll
            for (int j = 0; j < 4; j++) acc[mi][ni][j] = 0.f;

    for (int k0 = 0; k0 < I_DIM; k0 += BK) {
#pragma unroll
        for (int l = 0; l < 4; l++) {
            int idx = tid + l * 256;
            int r = idx >> 3, c4 = (idx & 7) * 4;
            float4 v = *(const float4*)(aP[l] + k0);
            uint4 u; u.x = f2tf32(v.x); u.y = f2tf32(v.y); u.z = f2tf32(v.z); u.w = f2tf32(v.w);
            *(uint4*)&sA[r][c4] = u;
        }
#pragma unroll
        for (int l = 0; l < 2; l++) {
            int idx = tid + l * 256;
            int n = idx >> 3, c4 = (idx & 7) * 4;
            float4 v = *(const float4*)(bP[l] + k0);
            uint4 u; u.x = f2tf32(v.x); u.y = f2tf32(v.y); u.z = f2tf32(v.z); u.w = f2tf32(v.w);
            *(uint4*)&sB[n][c4] = u;
        }
        __syncthreads();
#pragma unroll
        for (int kk = 0; kk < BK; kk += 8) {
            uint32_t a[2][4];
#pragma unroll
            for (int mi = 0; mi < 2; mi++) {
                int row = wm + mi * 16 + gID;
                a[mi][0] = sA[row][kk + tig];
                a[mi][1] = sA[row + 8][kk + tig];
                a[mi][2] = sA[row][kk + tig + 4];
                a[mi][3] = sA[row + 8][kk + tig + 4];
            }
#pragma unroll
            for (int ni = 0; ni < 4; ni++) {
                int n = wn + ni * 8 + gID;
                uint32_t b[2] = { sB[n][kk + tig], sB[n][kk + tig + 4] };
#pragma unroll
                for (int mi = 0; mi < 2; mi++) mma8(acc[mi][ni], a[mi], b);
            }
        }
        __syncthreads();
    }

    // epilogue: scatter back to original token rows (padding rows skipped)
#pragma unroll
    for (int mi = 0; mi < 2; mi++) {
#pragma unroll
        for (int ni = 0; ni < 4; ni++) {
#pragma unroll
            for (int half = 0; half < 2; half++) {
                int row = wm + mi * 16 + gID + half * 8;
                int tok = sTok[row];
                if (tok >= 0) {
                    int col = nBase + wn + ni * 8 + tig * 2;
                    *(float2*)&out[(size_t)tok * H_DIM + col] =
                        make_float2(acc[mi][ni][half * 2 + 0], acc[mi][ni][half * 2 + 1]);
                }
            }
        }
    }
}

// ---------------- launch ----------------
extern "C" void kernel_launch(void* const* d_in, const int* in_sizes, int n_in,
                              void* d_out, int out_size) {
    const float* hs     = (const float*)d_in[0];   // [B,S,H] fp32
    const float* gate_w = (const float*)d_in[1];   // [E,H]
    const float* w_gate = (const float*)d_in[2];   // [E,I,H]
    const float* w_up   = (const float*)d_in[3];   // [E,I,H]
    const float* w_down = (const float*)d_in[4];   // [E,H,I]
    float* out = (float*)d_out;                    // [B,S,H] fp32

    k_init<<<(PERM_N + 255) / 256, 256>>>();
    k_router<<<T_TOK / 8, 256>>>(hs, gate_w);
    k_plan<<<1, 1>>>();
    k_scatter<<<T_TOK / 256, 256>>>();

    dim3 g1(MAXTILES, I_DIM / BN);   // 72 x 8
    k_gemm1<<<g1, 256>>>(hs, w_gate, w_up);

    dim3 g2(MAXTILES, H_DIM / BN);   // 72 x 16
    k_gemm2<<<g2, 256>>>(w_down, out);
}